// round 5
// baseline (speedup 1.0000x reference)
#include <cuda_runtime.h>
#include <cuda_bf16.h>
#include <cstdint>

#define NENT   100000
#define NEDGE  500000
#define NSEED  10000
#define DIM    128
#define NTILE  782                  // ceil(NENT/128)
#define NROWPAD (NTILE * 128)       // 100096

// dense tiling
#define BM 128
#define BN 64
#define LDA 132                     // padded stride for A tile (floats)
#define LDB 132                     // padded stride for W tiles (floats)
#define SMEM_D ((BM * LDA + 2 * BN * LDB) * 4)   // 135168 bytes

// ---------------- device scratch ----------------
__device__ int   g_cntbuf[2][NENT];
__device__ int   g_rowptr[NENT + 1];
__device__ int   g_cursor[NENT];
__device__ int   g_col[2 * NEDGE];
__device__ float g_rinv[NENT];
__device__ float g_hid[(size_t)NENT * DIM];
__device__ float g_agg[(size_t)NROWPAD * DIM];          // zero-padded tail rows
__device__ uint32_t g_Whi[2][DIM * DIM];                // [layer], transposed [n][k], tf32 bits
__device__ uint32_t g_Wlo[2][DIM * DIM];

// ---------------- helpers ----------------
__device__ __forceinline__ uint32_t f2tf32(float x) {
    uint32_t u;
    asm("cvt.rna.tf32.f32 %0, %1;" : "=r"(u) : "f"(x));
    return u;
}
__device__ __forceinline__ void mma_tf32(float* c, const uint32_t* a, const uint32_t* b) {
    asm volatile(
        "mma.sync.aligned.m16n8k8.row.col.f32.tf32.tf32.f32 "
        "{%0,%1,%2,%3}, {%4,%5,%6,%7}, {%8,%9}, {%0,%1,%2,%3};"
        : "+f"(c[0]), "+f"(c[1]), "+f"(c[2]), "+f"(c[3])
        : "r"(a[0]), "r"(a[1]), "r"(a[2]), "r"(a[3]), "r"(b[0]), "r"(b[1]));
}

// ---------------- W prep (tf32 hi/lo, transposed) + zero cnt ----------------
__global__ void k_wprep(const float* __restrict__ W, int which) {
    if (blockIdx.x == 0) {
        int n = threadIdx.x;
        for (int k = 0; k < DIM; k++) {
            float w = W[k * DIM + n];
            uint32_t hi = f2tf32(w);
            float lo = w - __uint_as_float(hi);
            g_Whi[which][n * DIM + k] = hi;
            g_Wlo[which][n * DIM + k] = f2tf32(lo);
        }
    } else {
        int i = (blockIdx.x - 1) * 128 + threadIdx.x;
        if (i < NENT) g_cntbuf[which][i] = 0;
    }
}

// ---------------- graph build ----------------
__global__ void k_count(const int* __restrict__ edges, int which) {
    int i = blockIdx.x * blockDim.x + threadIdx.x;
    if (i < NEDGE) {
        atomicAdd(&g_cntbuf[which][edges[2 * i]], 1);
        atomicAdd(&g_cntbuf[which][edges[2 * i + 1]], 1);
    }
}

// single-block full scan + prep (rowptr, cursor, rinv)
__global__ void k_scan(int which) {
    __shared__ int wsum[32];
    __shared__ int s_carry;
    const int* cnt = g_cntbuf[which];
    int tid = threadIdx.x, lane = tid & 31, w = tid >> 5;
    if (tid == 0) s_carry = 0;
    __syncthreads();
    for (int c = 0; c < 98; c++) {
        int i = c * 1024 + tid;
        int v = (i < NENT) ? cnt[i] : 0;
        int x = v;
        #pragma unroll
        for (int off = 1; off < 32; off <<= 1) {
            int t = __shfl_up_sync(0xffffffffu, x, off);
            if (lane >= off) x += t;
        }
        if (lane == 31) wsum[w] = x;
        __syncthreads();
        if (w == 0) {
            int y = wsum[lane];
            #pragma unroll
            for (int off = 1; off < 32; off <<= 1) {
                int t = __shfl_up_sync(0xffffffffu, y, off);
                if (lane >= off) y += t;
            }
            wsum[lane] = y;
        }
        __syncthreads();
        int blockoff = (w > 0) ? wsum[w - 1] : 0;
        int excl = s_carry + blockoff + x - v;
        int total = wsum[31];
        if (i < NENT) {
            g_rowptr[i] = excl;
            g_cursor[i] = excl;
            g_rinv[i] = rsqrtf((float)(v + 1));
        }
        __syncthreads();
        if (tid == 0) s_carry += total;
        __syncthreads();
    }
    if (tid == 0) g_rowptr[NENT] = 2 * NEDGE;
}

__global__ void k_fill(const int* __restrict__ edges) {
    int i = blockIdx.x * blockDim.x + threadIdx.x;
    if (i < NEDGE) {
        int a = edges[2 * i], b = edges[2 * i + 1];
        int p = atomicAdd(&g_cursor[b], 1); g_col[p] = a;
        int q = atomicAdd(&g_cursor[a], 1); g_col[q] = b;
    }
}

// ---------------- aggregation: g_agg[v] = sum_u x[u]*rinv[u]*rinv[v] + x[v]*rinv[v]^2 ----------------
__global__ void k_agg(const float* __restrict__ x) {
    int gw   = (blockIdx.x * blockDim.x + threadIdx.x) >> 5;
    int lane = threadIdx.x & 31;
    if (gw >= NENT) return;
    int v = gw;
    int beg = g_rowptr[v], end = g_rowptr[v + 1];
    float rv = g_rinv[v];
    const float4* x4 = (const float4*)x;
    float4 a = x4[(size_t)v * 32 + lane];
    float selfn = rv * rv;
    float4 acc;
    acc.x = a.x * selfn; acc.y = a.y * selfn; acc.z = a.z * selfn; acc.w = a.w * selfn;
    for (int e = beg; e < end; e++) {
        int u = g_col[e];
        float nm = rv * g_rinv[u];
        float4 xu = x4[(size_t)u * 32 + lane];
        acc.x = fmaf(xu.x, nm, acc.x);
        acc.y = fmaf(xu.y, nm, acc.y);
        acc.z = fmaf(xu.z, nm, acc.z);
        acc.w = fmaf(xu.w, nm, acc.w);
    }
    ((float4*)g_agg)[(size_t)v * 32 + lane] = acc;
}

// ---------------- dense: out = relu(g_agg @ W + xin), split-tf32 mma ----------------
__global__ void __launch_bounds__(256, 1) k_dense_mma(const float* __restrict__ xin, int which,
                                                      float* __restrict__ out) {
    extern __shared__ float smem[];
    float* sA   = smem;                      // [BM][LDA]
    float* sBhi = sA + BM * LDA;             // [BN][LDB]
    float* sBlo = sBhi + BN * LDB;

    int tid = threadIdx.x;
    int bm = blockIdx.x, bn = blockIdx.y;

    // stage A (128x128 fp32) coalesced, padded stride
    {
        const float4* src = (const float4*)(g_agg + (size_t)bm * BM * DIM);
        #pragma unroll
        for (int t = 0; t < 16; t++) {
            int idx4 = tid + t * 256;                 // 4096 float4s
            int row = idx4 >> 5, col4 = (idx4 & 31) << 2;
            *(float4*)(sA + row * LDA + col4) = src[idx4];
        }
    }
    // stage W hi/lo (64x128 each), transposed layout [n][k]
    {
        const float4* shi = (const float4*)(g_Whi[which] + bn * BN * DIM);
        const float4* slo = (const float4*)(g_Wlo[which] + bn * BN * DIM);
        #pragma unroll
        for (int t = 0; t < 8; t++) {
            int idx4 = tid + t * 256;                 // 2048 float4s
            int row = idx4 >> 5, col4 = (idx4 & 31) << 2;
            *(float4*)(sBhi + row * LDB + col4) = shi[idx4];
            *(float4*)(sBlo + row * LDB + col4) = slo[idx4];
        }
    }
    __syncthreads();

    int wid = tid >> 5, lane = tid & 31;
    int warp_m = wid & 3, warp_n = wid >> 2;          // 4x2 warp grid, 32x32 each
    int group = lane >> 2, tig = lane & 3;

    float acc[2][4][4];
    #pragma unroll
    for (int mi = 0; mi < 2; mi++)
        #pragma unroll
        for (int ni = 0; ni < 4; ni++)
            #pragma unroll
            for (int q = 0; q < 4; q++) acc[mi][ni][q] = 0.f;

    const float* pA = sA + (warp_m * 32 + group) * LDA + tig;
    const float* pB_hi = sBhi + (warp_n * 32 + group) * LDB + tig;
    const float* pB_lo = sBlo + (warp_n * 32 + group) * LDB + tig;

    #pragma unroll
    for (int kk = 0; kk < 16; kk++) {
        int k0 = kk * 8;
        uint32_t ahi[2][4], alo[2][4];
        #pragma unroll
        for (int mi = 0; mi < 2; mi++) {
            float r0 = pA[(mi * 16) * LDA + k0];
            float r1 = pA[(mi * 16 + 8) * LDA + k0];
            float r2 = pA[(mi * 16) * LDA + k0 + 4];
            float r3 = pA[(mi * 16 + 8) * LDA + k0 + 4];
            ahi[mi][0] = f2tf32(r0); alo[mi][0] = f2tf32(r0 - __uint_as_float(ahi[mi][0]));
            ahi[mi][1] = f2tf32(r1); alo[mi][1] = f2tf32(r1 - __uint_as_float(ahi[mi][1]));
            ahi[mi][2] = f2tf32(r2); alo[mi][2] = f2tf32(r2 - __uint_as_float(ahi[mi][2]));
            ahi[mi][3] = f2tf32(r3); alo[mi][3] = f2tf32(r3 - __uint_as_float(ahi[mi][3]));
        }
        #pragma unroll
        for (int ni = 0; ni < 4; ni++) {
            uint32_t bhi[2], blo[2];
            bhi[0] = __float_as_uint(pB_hi[(ni * 8 - (group & 24)) * LDB + k0]);
            bhi[1] = __float_as_uint(pB_hi[(ni * 8 - (group & 24)) * LDB + k0 + 4]);
            blo[0] = __float_as_uint(pB_lo[(ni * 8 - (group & 24)) * LDB + k0]);
            blo[1] = __float_as_uint(pB_lo[(ni * 8 - (group & 24)) * LDB + k0 + 4]);
            #pragma unroll
            for (int mi = 0; mi < 2; mi++) {
                mma_tf32(acc[mi][ni], ahi[mi], bhi);
                mma_tf32(acc[mi][ni], alo[mi], bhi);
                mma_tf32(acc[mi][ni], ahi[mi], blo);
            }
        }
    }

    // epilogue: residual + relu
    #pragma unroll
    for (int mi = 0; mi < 2; mi++) {
        int r0 = bm * BM + warp_m * 32 + mi * 16 + group;
        int r1 = r0 + 8;
        #pragma unroll
        for (int ni = 0; ni < 4; ni++) {
            int c = bn * BN + warp_n * 32 + ni * 8 + tig * 2;
            if (r0 < NENT) {
                float2 xv = *(const float2*)(xin + (size_t)r0 * DIM + c);
                float2 o;
                o.x = fmaxf(acc[mi][ni][0] + xv.x, 0.f);
                o.y = fmaxf(acc[mi][ni][1] + xv.y, 0.f);
                *(float2*)(out + (size_t)r0 * DIM + c) = o;
            }
            if (r1 < NENT) {
                float2 xv = *(const float2*)(xin + (size_t)r1 * DIM + c);
                float2 o;
                o.x = fmaxf(acc[mi][ni][2] + xv.x, 0.f);
                o.y = fmaxf(acc[mi][ni][3] + xv.y, 0.f);
                *(float2*)(out + (size_t)r1 * DIM + c) = o;
            }
        }
    }
}

// ---------------- seed gather ----------------
__global__ void k_seed(const int* __restrict__ seeds, const float* __restrict__ ent,
                       float* __restrict__ out) {
    int gw   = (blockIdx.x * blockDim.x + threadIdx.x) >> 5;
    int lane = threadIdx.x & 31;
    if (gw >= NSEED) return;
    int s = seeds[gw];
    ((float4*)out)[(size_t)gw * 32 + lane] = ((const float4*)ent)[(size_t)s * 32 + lane];
}

// ---------------- launch ----------------
extern "C" void kernel_launch(void* const* d_in, const int* in_sizes, int n_in,
                              void* d_out, int out_size) {
    const int*   sr_seeds = (const int*)d_in[0];
    const int*   tg_seeds = (const int*)d_in[1];
    const float* emb_sr   = (const float*)d_in[4];
    const float* emb_tg   = (const float*)d_in[5];
    const int*   edges_sr = (const int*)d_in[6];
    const int*   edges_tg = (const int*)d_in[7];
    const float* W1       = (const float*)d_in[8];
    const float* W2       = (const float*)d_in[9];

    float* out         = (float*)d_out;
    float* sr_seed_out = out;
    float* tg_seed_out = out + (size_t)NSEED * DIM;
    float* sr_ent_out  = out + (size_t)2 * NSEED * DIM;
    float* tg_ent_out  = out + (size_t)2 * NSEED * DIM + (size_t)NENT * DIM;

    cudaFuncSetAttribute(k_dense_mma, cudaFuncAttributeMaxDynamicSharedMemorySize, SMEM_D);

    float* hid = nullptr;
    cudaGetSymbolAddress((void**)&hid, g_hid);

    int tE = (NEDGE + 255) / 256;
    dim3 gridD(NTILE, 2);

    k_wprep<<<783, 128>>>(W1, 0);
    k_wprep<<<783, 128>>>(W2, 1);

    for (int g = 0; g < 2; g++) {
        const int*   edges = g ? edges_tg : edges_sr;
        const float* emb   = g ? emb_tg : emb_sr;
        const int*   seeds = g ? tg_seeds : sr_seeds;
        float* ent_out  = g ? tg_ent_out : sr_ent_out;
        float* seed_out = g ? tg_seed_out : sr_seed_out;

        k_count<<<tE, 256>>>(edges, g);
        k_scan<<<1, 1024>>>(g);
        k_fill<<<tE, 256>>>(edges);

        k_agg<<<12500, 256>>>(emb);
        k_dense_mma<<<gridD, 256, SMEM_D>>>(emb, 0, hid);
        k_agg<<<12500, 256>>>(hid);
        k_dense_mma<<<gridD, 256, SMEM_D>>>(hid, 1, ent_out);

        k_seed<<<(NSEED * 32 + 255) / 256, 256>>>(seeds, ent_out, seed_out);
    }
}

// round 6
// speedup vs baseline: 1.2659x; 1.2659x over previous
#include <cuda_runtime.h>
#include <cuda_bf16.h>
#include <cstdint>

#define NENT   100000
#define NEDGE  500000
#define NSEED  10000
#define DIM    128
#define NTILE  782                  // ceil(NENT/128)
#define NROWPAD (NTILE * 128)       // 100096
#define NBLK_SCAN 98                // ceil(NENT/1024)

// dense tiling
#define BM 128
#define BN 64
#define LDA 132                     // padded stride for A tile (floats)
#define LDB 132                     // padded stride for W tiles (floats)
#define SMEM_D ((BM * LDA + 2 * BN * LDB) * 4)   // 135168 bytes

// ---------------- device scratch ----------------
__device__ int   g_cntbuf[2][NENT];
__device__ int   g_rowptr[NENT + 1];
__device__ int   g_cursor[NENT];
__device__ int   g_col[2 * NEDGE];
__device__ float g_rinv[NENT];
__device__ float g_hid[(size_t)NENT * DIM];
__device__ float g_agg[(size_t)NROWPAD * DIM];          // zero-padded tail rows
__device__ uint32_t g_Whi[2][DIM * DIM];                // [layer], transposed [n][k], tf32 bits
__device__ uint32_t g_Wlo[2][DIM * DIM];
__device__ int   g_bsum[NBLK_SCAN];

// ---------------- helpers ----------------
__device__ __forceinline__ uint32_t f2tf32(float x) {
    uint32_t u;
    asm("cvt.rna.tf32.f32 %0, %1;" : "=r"(u) : "f"(x));
    return u;
}
__device__ __forceinline__ void mma_tf32(float* c, const uint32_t* a, const uint32_t* b) {
    asm volatile(
        "mma.sync.aligned.m16n8k8.row.col.f32.tf32.tf32.f32 "
        "{%0,%1,%2,%3}, {%4,%5,%6,%7}, {%8,%9}, {%0,%1,%2,%3};"
        : "+f"(c[0]), "+f"(c[1]), "+f"(c[2]), "+f"(c[3])
        : "r"(a[0]), "r"(a[1]), "r"(a[2]), "r"(a[3]), "r"(b[0]), "r"(b[1]));
}

// ---------------- W prep (both layers) + zero both cnt arrays ----------------
__global__ void k_wprep(const float* __restrict__ W1, const float* __restrict__ W2) {
    if (blockIdx.x < 2) {
        const float* W = blockIdx.x ? W2 : W1;
        int which = blockIdx.x;
        int n = threadIdx.x;
        for (int k = 0; k < DIM; k++) {
            float w = W[k * DIM + n];
            uint32_t hi = f2tf32(w);
            float lo = w - __uint_as_float(hi);
            g_Whi[which][n * DIM + k] = hi;
            g_Wlo[which][n * DIM + k] = f2tf32(lo);
        }
    } else {
        int i = (blockIdx.x - 2) * 128 + threadIdx.x;
        if (i < NENT) { g_cntbuf[0][i] = 0; g_cntbuf[1][i] = 0; }
    }
}

// ---------------- graph build ----------------
__global__ void k_count(const int* __restrict__ edges, int which) {
    int i = blockIdx.x * blockDim.x + threadIdx.x;
    if (i < NEDGE) {
        int2 e = ((const int2*)edges)[i];
        atomicAdd(&g_cntbuf[which][e.x], 1);
        atomicAdd(&g_cntbuf[which][e.y], 1);
    }
}

// per-block exclusive scan + rinv + block sums
__global__ void k_scan1(int which) {
    __shared__ int wsum[32];
    const int* cnt = g_cntbuf[which];
    int tid = threadIdx.x, lane = tid & 31, w = tid >> 5;
    int i = blockIdx.x * 1024 + tid;
    int v = (i < NENT) ? cnt[i] : 0;
    int x = v;
    #pragma unroll
    for (int off = 1; off < 32; off <<= 1) {
        int t = __shfl_up_sync(0xffffffffu, x, off);
        if (lane >= off) x += t;
    }
    if (lane == 31) wsum[w] = x;
    __syncthreads();
    if (w == 0) {
        int y = wsum[lane];
        #pragma unroll
        for (int off = 1; off < 32; off <<= 1) {
            int t = __shfl_up_sync(0xffffffffu, y, off);
            if (lane >= off) y += t;
        }
        wsum[lane] = y;
    }
    __syncthreads();
    int excl = ((w > 0) ? wsum[w - 1] : 0) + x - v;
    if (i < NENT) {
        g_rowptr[i] = excl;
        g_rinv[i] = rsqrtf((float)(v + 1));
    }
    if (tid == 1023) g_bsum[blockIdx.x] = wsum[31];
}

// add cross-block offset (each block reduces the block-sums below it)
__global__ void k_scanadd(int which) {
    __shared__ int s_off;
    int tid = threadIdx.x;
    if (tid < 32) {
        int s = 0;
        #pragma unroll
        for (int c = tid; c < NBLK_SCAN; c += 32)
            if (c < (int)blockIdx.x) s += g_bsum[c];
        #pragma unroll
        for (int o = 16; o; o >>= 1) s += __shfl_xor_sync(0xffffffffu, s, o);
        if (tid == 0) s_off = s;
    }
    __syncthreads();
    int i = blockIdx.x * 1024 + tid;
    if (i < NENT) {
        int r = g_rowptr[i] + s_off;
        g_rowptr[i] = r;
        g_cursor[i] = r;
    }
    if (i == 0) g_rowptr[NENT] = 2 * NEDGE;
}

__global__ void k_fill(const int* __restrict__ edges) {
    int i = blockIdx.x * blockDim.x + threadIdx.x;
    if (i < NEDGE) {
        int2 e = ((const int2*)edges)[i];
        int p = atomicAdd(&g_cursor[e.y], 1); g_col[p] = e.x;
        int q = atomicAdd(&g_cursor[e.x], 1); g_col[q] = e.y;
    }
}

// ---------------- aggregation: g_agg[v] = sum_u x[u]*rinv[u]*rinv[v] + x[v]*rinv[v]^2 ----------------
__global__ void k_aggc(const float* __restrict__ x) {
    int gw   = (blockIdx.x * blockDim.x + threadIdx.x) >> 5;
    int lane = threadIdx.x & 31;
    if (gw >= NENT) return;
    int v = gw;
    int beg = g_rowptr[v], end = g_rowptr[v + 1];
    float rv = g_rinv[v];
    const float4* x4 = (const float4*)x;
    float4 a = x4[(size_t)v * 32 + lane];
    float selfn = rv * rv;
    float4 acc;
    acc.x = a.x * selfn; acc.y = a.y * selfn; acc.z = a.z * selfn; acc.w = a.w * selfn;
    int e = beg;
    for (; e + 4 <= end; e += 4) {
        int u0 = g_col[e], u1 = g_col[e + 1], u2 = g_col[e + 2], u3 = g_col[e + 3];
        float n0 = rv * g_rinv[u0], n1 = rv * g_rinv[u1];
        float n2 = rv * g_rinv[u2], n3 = rv * g_rinv[u3];
        float4 a0 = x4[(size_t)u0 * 32 + lane];
        float4 a1 = x4[(size_t)u1 * 32 + lane];
        float4 a2 = x4[(size_t)u2 * 32 + lane];
        float4 a3 = x4[(size_t)u3 * 32 + lane];
        acc.x = fmaf(a0.x, n0, acc.x); acc.y = fmaf(a0.y, n0, acc.y);
        acc.z = fmaf(a0.z, n0, acc.z); acc.w = fmaf(a0.w, n0, acc.w);
        acc.x = fmaf(a1.x, n1, acc.x); acc.y = fmaf(a1.y, n1, acc.y);
        acc.z = fmaf(a1.z, n1, acc.z); acc.w = fmaf(a1.w, n1, acc.w);
        acc.x = fmaf(a2.x, n2, acc.x); acc.y = fmaf(a2.y, n2, acc.y);
        acc.z = fmaf(a2.z, n2, acc.z); acc.w = fmaf(a2.w, n2, acc.w);
        acc.x = fmaf(a3.x, n3, acc.x); acc.y = fmaf(a3.y, n3, acc.y);
        acc.z = fmaf(a3.z, n3, acc.z); acc.w = fmaf(a3.w, n3, acc.w);
    }
    for (; e < end; e++) {
        int u = g_col[e];
        float nm = rv * g_rinv[u];
        float4 xu = x4[(size_t)u * 32 + lane];
        acc.x = fmaf(xu.x, nm, acc.x);
        acc.y = fmaf(xu.y, nm, acc.y);
        acc.z = fmaf(xu.z, nm, acc.z);
        acc.w = fmaf(xu.w, nm, acc.w);
    }
    ((float4*)g_agg)[(size_t)v * 32 + lane] = acc;
}

// ---------------- dense: out = relu(g_agg @ W + xin), split-tf32 mma ----------------
__global__ void __launch_bounds__(256, 1) k_dense_mma(const float* __restrict__ xin, int which,
                                                      float* __restrict__ out) {
    extern __shared__ float smem[];
    float* sA   = smem;                      // [BM][LDA]
    float* sBhi = sA + BM * LDA;             // [BN][LDB]
    float* sBlo = sBhi + BN * LDB;

    int tid = threadIdx.x;
    int bm = blockIdx.x, bn = blockIdx.y;

    {
        const float4* src = (const float4*)(g_agg + (size_t)bm * BM * DIM);
        #pragma unroll
        for (int t = 0; t < 16; t++) {
            int idx4 = tid + t * 256;
            int row = idx4 >> 5, col4 = (idx4 & 31) << 2;
            *(float4*)(sA + row * LDA + col4) = src[idx4];
        }
    }
    {
        const float4* shi = (const float4*)(g_Whi[which] + bn * BN * DIM);
        const float4* slo = (const float4*)(g_Wlo[which] + bn * BN * DIM);
        #pragma unroll
        for (int t = 0; t < 8; t++) {
            int idx4 = tid + t * 256;
            int row = idx4 >> 5, col4 = (idx4 & 31) << 2;
            *(float4*)(sBhi + row * LDB + col4) = shi[idx4];
            *(float4*)(sBlo + row * LDB + col4) = slo[idx4];
        }
    }
    __syncthreads();

    int wid = tid >> 5, lane = tid & 31;
    int warp_m = wid & 3, warp_n = wid >> 2;
    int group = lane >> 2, tig = lane & 3;

    float acc[2][4][4];
    #pragma unroll
    for (int mi = 0; mi < 2; mi++)
        #pragma unroll
        for (int ni = 0; ni < 4; ni++)
            #pragma unroll
            for (int q = 0; q < 4; q++) acc[mi][ni][q] = 0.f;

    const float* pA = sA + (warp_m * 32 + group) * LDA + tig;
    const float* pB_hi = sBhi + (warp_n * 32 + group) * LDB + tig;
    const float* pB_lo = sBlo + (warp_n * 32 + group) * LDB + tig;

    #pragma unroll
    for (int kk = 0; kk < 16; kk++) {
        int k0 = kk * 8;
        uint32_t ahi[2][4], alo[2][4];
        #pragma unroll
        for (int mi = 0; mi < 2; mi++) {
            float r0 = pA[(mi * 16) * LDA + k0];
            float r1 = pA[(mi * 16 + 8) * LDA + k0];
            float r2 = pA[(mi * 16) * LDA + k0 + 4];
            float r3 = pA[(mi * 16 + 8) * LDA + k0 + 4];
            ahi[mi][0] = f2tf32(r0); alo[mi][0] = f2tf32(r0 - __uint_as_float(ahi[mi][0]));
            ahi[mi][1] = f2tf32(r1); alo[mi][1] = f2tf32(r1 - __uint_as_float(ahi[mi][1]));
            ahi[mi][2] = f2tf32(r2); alo[mi][2] = f2tf32(r2 - __uint_as_float(ahi[mi][2]));
            ahi[mi][3] = f2tf32(r3); alo[mi][3] = f2tf32(r3 - __uint_as_float(ahi[mi][3]));
        }
        #pragma unroll
        for (int ni = 0; ni < 4; ni++) {
            uint32_t bhi[2], blo[2];
            bhi[0] = __float_as_uint(pB_hi[(ni * 8 - (group & 24)) * LDB + k0]);
            bhi[1] = __float_as_uint(pB_hi[(ni * 8 - (group & 24)) * LDB + k0 + 4]);
            blo[0] = __float_as_uint(pB_lo[(ni * 8 - (group & 24)) * LDB + k0]);
            blo[1] = __float_as_uint(pB_lo[(ni * 8 - (group & 24)) * LDB + k0 + 4]);
            #pragma unroll
            for (int mi = 0; mi < 2; mi++) {
                mma_tf32(acc[mi][ni], ahi[mi], bhi);
                mma_tf32(acc[mi][ni], alo[mi], bhi);
                mma_tf32(acc[mi][ni], ahi[mi], blo);
            }
        }
    }

    #pragma unroll
    for (int mi = 0; mi < 2; mi++) {
        int r0 = bm * BM + warp_m * 32 + mi * 16 + group;
        int r1 = r0 + 8;
        #pragma unroll
        for (int ni = 0; ni < 4; ni++) {
            int c = bn * BN + warp_n * 32 + ni * 8 + tig * 2;
            if (r0 < NENT) {
                float2 xv = *(const float2*)(xin + (size_t)r0 * DIM + c);
                float2 o;
                o.x = fmaxf(acc[mi][ni][0] + xv.x, 0.f);
                o.y = fmaxf(acc[mi][ni][1] + xv.y, 0.f);
                *(float2*)(out + (size_t)r0 * DIM + c) = o;
            }
            if (r1 < NENT) {
                float2 xv = *(const float2*)(xin + (size_t)r1 * DIM + c);
                float2 o;
                o.x = fmaxf(acc[mi][ni][2] + xv.x, 0.f);
                o.y = fmaxf(acc[mi][ni][3] + xv.y, 0.f);
                *(float2*)(out + (size_t)r1 * DIM + c) = o;
            }
        }
    }
}

// ---------------- seed gather ----------------
__global__ void k_seed(const int* __restrict__ seeds, const float* __restrict__ ent,
                       float* __restrict__ out) {
    int gw   = (blockIdx.x * blockDim.x + threadIdx.x) >> 5;
    int lane = threadIdx.x & 31;
    if (gw >= NSEED) return;
    int s = seeds[gw];
    ((float4*)out)[(size_t)gw * 32 + lane] = ((const float4*)ent)[(size_t)s * 32 + lane];
}

// ---------------- launch ----------------
extern "C" void kernel_launch(void* const* d_in, const int* in_sizes, int n_in,
                              void* d_out, int out_size) {
    const int*   sr_seeds = (const int*)d_in[0];
    const int*   tg_seeds = (const int*)d_in[1];
    const float* emb_sr   = (const float*)d_in[4];
    const float* emb_tg   = (const float*)d_in[5];
    const int*   edges_sr = (const int*)d_in[6];
    const int*   edges_tg = (const int*)d_in[7];
    const float* W1       = (const float*)d_in[8];
    const float* W2       = (const float*)d_in[9];

    float* out         = (float*)d_out;
    float* sr_seed_out = out;
    float* tg_seed_out = out + (size_t)NSEED * DIM;
    float* sr_ent_out  = out + (size_t)2 * NSEED * DIM;
    float* tg_ent_out  = out + (size_t)2 * NSEED * DIM + (size_t)NENT * DIM;

    cudaFuncSetAttribute(k_dense_mma, cudaFuncAttributeMaxDynamicSharedMemorySize, SMEM_D);

    float* hid = nullptr;
    cudaGetSymbolAddress((void**)&hid, g_hid);

    int tE = (NEDGE + 255) / 256;
    dim3 gridD(NTILE, 2);

    k_wprep<<<784, 128>>>(W1, W2);

    for (int g = 0; g < 2; g++) {
        const int*   edges = g ? edges_tg : edges_sr;
        const float* emb   = g ? emb_tg : emb_sr;
        const int*   seeds = g ? tg_seeds : sr_seeds;
        float* ent_out  = g ? tg_ent_out : sr_ent_out;
        float* seed_out = g ? tg_seed_out : sr_seed_out;

        k_count<<<tE, 256>>>(edges, g);
        k_scan1<<<NBLK_SCAN, 1024>>>(g);
        k_scanadd<<<NBLK_SCAN, 1024>>>(g);
        k_fill<<<tE, 256>>>(edges);

        k_aggc<<<12500, 256>>>(emb);
        k_dense_mma<<<gridD, 256, SMEM_D>>>(emb, 0, hid);
        k_aggc<<<12500, 256>>>(hid);
        k_dense_mma<<<gridD, 256, SMEM_D>>>(hid, 1, ent_out);

        k_seed<<<(NSEED * 32 + 255) / 256, 256>>>(seeds, ent_out, seed_out);
    }
}